// round 1
// baseline (speedup 1.0000x reference)
#include <cuda_runtime.h>
#include <math.h>

#define NB 2
#define NH 12
#define HD 64
#define SEQ 2048
#define CDIM 768
#define LSMAX 4.605170185988092f
#define NEPS 1e-12f

// Scratch (allocation-free rule: __device__ globals)
__device__ float g_qn[(size_t)NB*NH*SEQ*HD];   // normalized q * exp(min(logit_scale,MAX)), [N,H,L,D]
__device__ float g_kn[(size_t)NB*NH*SEQ*HD];   // normalized k, [N,H,L,D]
__device__ float g_v [(size_t)NB*NH*SEQ*HD];   // v, [N,H,L,D]
__device__ float g_ao[(size_t)NB*SEQ*CDIM];    // attention output, [N,L,C]

// ---------------------------------------------------------------------------
// Kernel 1: QKV projection (M=4096, K=768, per-block 64x64 tile = one head slot)
// + bias + L2 norm (q,k) + logit-scale fold (q) + transpose to [N,H,L,D]
// grid: (36, 64)  block: 256
// ---------------------------------------------------------------------------
__global__ void qkv_kernel(const float* __restrict__ x,
                           const float* __restrict__ W,
                           const float* __restrict__ bias,
                           const float* __restrict__ logit_scale)
{
    const int comp = blockIdx.x / NH;        // 0=q, 1=k, 2=v
    const int h    = blockIdx.x % NH;
    const int m0   = blockIdx.y * 64;
    const int f0   = comp * CDIM + h * HD;
    const int tid  = threadIdx.x;
    const int tx   = tid & 15, ty = tid >> 4;

    __shared__ float As[64][17];
    __shared__ float Bs[64][17];
    __shared__ float Cs[64][65];
    __shared__ float rnorm[64];

    float acc[4][4] = {};
    for (int k0 = 0; k0 < CDIM; k0 += 16) {
        #pragma unroll
        for (int i = 0; i < 4; i++) {
            int idx = tid + i * 256;
            int r = idx >> 4, c = idx & 15;
            As[r][c] = x[(size_t)(m0 + r) * CDIM + k0 + c];
            Bs[r][c] = W[(size_t)(f0 + r) * CDIM + k0 + c];
        }
        __syncthreads();
        #pragma unroll
        for (int k = 0; k < 16; k++) {
            float a[4], b[4];
            #pragma unroll
            for (int i = 0; i < 4; i++) a[i] = As[ty * 4 + i][k];
            #pragma unroll
            for (int j = 0; j < 4; j++) b[j] = Bs[tx * 4 + j][k];
            #pragma unroll
            for (int i = 0; i < 4; i++)
                #pragma unroll
                for (int j = 0; j < 4; j++) acc[i][j] += a[i] * b[j];
        }
        __syncthreads();
    }

    #pragma unroll
    for (int i = 0; i < 4; i++)
        #pragma unroll
        for (int j = 0; j < 4; j++)
            Cs[ty * 4 + i][tx * 4 + j] = acc[i][j] + bias[f0 + tx * 4 + j];
    __syncthreads();

    if (tid < 64) {
        float s = 1.0f;
        if (comp < 2) {
            float ss = 0.f;
            #pragma unroll 8
            for (int d = 0; d < HD; d++) { float t = Cs[tid][d]; ss += t * t; }
            s = 1.0f / fmaxf(sqrtf(ss), NEPS);
            if (comp == 0) s *= __expf(fminf(logit_scale[h], LSMAX));
        }
        rnorm[tid] = s;
    }
    __syncthreads();

    float* out = (comp == 0) ? g_qn : (comp == 1) ? g_kn : g_v;
    for (int idx = tid; idx < 64 * 64; idx += 256) {
        int r = idx >> 6, d = idx & 63;
        int m = m0 + r;
        int n = m / SEQ, l = m % SEQ;
        out[(((size_t)n * NH + h) * SEQ + l) * HD + d] = Cs[r][d] * rnorm[r];
    }
}

// ---------------------------------------------------------------------------
// Kernel 2: flash attention, BM=BN=64, D=64, fp32
// grid: (32, 12, 2)  block: 256, dynamic smem: 4 tiles
// ---------------------------------------------------------------------------
#define FLASH_SMEM (4 * 64 * 65 * 4)

__global__ void flash_kernel(const float* __restrict__ mask,
                             const float* __restrict__ learned_scale)
{
    extern __shared__ float sm[];
    float (*Qs)[65] = (float(*)[65])sm;
    float (*Ks)[65] = Qs + 64;
    float (*Vs)[65] = Ks + 64;
    float (*Ps)[65] = Vs + 64;

    const int qt = blockIdx.x, h = blockIdx.y, n = blockIdx.z;
    const int q0 = qt * 64;
    const int tid = threadIdx.x;
    const int tx = tid & 15, ty = tid >> 4;
    const size_t base = (((size_t)n * NH + h) * SEQ) * HD;

    for (int idx = tid; idx < 64 * 64; idx += 256) {
        int r = idx >> 6, d = idx & 63;
        Qs[r][d] = g_qn[base + (size_t)(q0 + r) * HD + d];
    }

    float O[4][4] = {};
    float mrow[4], lrow[4];
    #pragma unroll
    for (int i = 0; i < 4; i++) { mrow[i] = -INFINITY; lrow[i] = 0.f; }

    for (int kt = 0; kt < SEQ / 64; kt++) {
        __syncthreads();   // prev PV done before overwriting K/V
        for (int idx = tid; idx < 64 * 64; idx += 256) {
            int r = idx >> 6, d = idx & 63;
            size_t off = base + (size_t)(kt * 64 + r) * HD + d;
            Ks[r][d] = g_kn[off];
            Vs[r][d] = g_v[off];
        }
        __syncthreads();

        // S = Q K^T
        float S[4][4] = {};
        #pragma unroll
        for (int k = 0; k < 64; k++) {
            float a[4], b[4];
            #pragma unroll
            for (int i = 0; i < 4; i++) a[i] = Qs[ty * 4 + i][k];
            #pragma unroll
            for (int j = 0; j < 4; j++) b[j] = Ks[tx * 4 + j][k];
            #pragma unroll
            for (int i = 0; i < 4; i++)
                #pragma unroll
                for (int j = 0; j < 4; j++) S[i][j] += a[i] * b[j];
        }
        // additive mask
        #pragma unroll
        for (int i = 0; i < 4; i++)
            #pragma unroll
            for (int j = 0; j < 4; j++)
                S[i][j] += mask[(size_t)(q0 + ty * 4 + i) * SEQ + kt * 64 + tx * 4 + j];

        // online softmax (row group = 16 lanes, xor<=8 stays inside group)
        #pragma unroll
        for (int i = 0; i < 4; i++) {
            float mx = fmaxf(fmaxf(S[i][0], S[i][1]), fmaxf(S[i][2], S[i][3]));
            mx = fmaxf(mx, __shfl_xor_sync(0xffffffff, mx, 1));
            mx = fmaxf(mx, __shfl_xor_sync(0xffffffff, mx, 2));
            mx = fmaxf(mx, __shfl_xor_sync(0xffffffff, mx, 4));
            mx = fmaxf(mx, __shfl_xor_sync(0xffffffff, mx, 8));
            float mnew = fmaxf(mrow[i], mx);
            float alpha = __expf(mrow[i] - mnew);
            mrow[i] = mnew;
            float rs = 0.f;
            #pragma unroll
            for (int j = 0; j < 4; j++) {
                S[i][j] = __expf(S[i][j] - mnew);
                rs += S[i][j];
            }
            rs += __shfl_xor_sync(0xffffffff, rs, 1);
            rs += __shfl_xor_sync(0xffffffff, rs, 2);
            rs += __shfl_xor_sync(0xffffffff, rs, 4);
            rs += __shfl_xor_sync(0xffffffff, rs, 8);
            lrow[i] = lrow[i] * alpha + rs;
            #pragma unroll
            for (int j = 0; j < 4; j++) {
                O[i][j] *= alpha;
                Ps[ty * 4 + i][tx * 4 + j] = S[i][j];
            }
        }
        __syncthreads();

        // O += P V
        #pragma unroll
        for (int k = 0; k < 64; k++) {
            float a[4], b[4];
            #pragma unroll
            for (int i = 0; i < 4; i++) a[i] = Ps[ty * 4 + i][k];
            #pragma unroll
            for (int j = 0; j < 4; j++) b[j] = Vs[k][tx * 4 + j];
            #pragma unroll
            for (int i = 0; i < 4; i++)
                #pragma unroll
                for (int j = 0; j < 4; j++) O[i][j] += a[i] * b[j];
        }
    }

    const float lsc = learned_scale[h];
    #pragma unroll
    for (int i = 0; i < 4; i++) {
        float inv = lsc / lrow[i];
        int l = q0 + ty * 4 + i;
        #pragma unroll
        for (int j = 0; j < 4; j++)
            g_ao[((size_t)n * SEQ + l) * CDIM + h * HD + tx * 4 + j] = O[i][j] * inv;
    }
}

// ---------------------------------------------------------------------------
// Kernel 3: out projection GEMM (4096x768 @ 768x768^T + bias) -> d_out
// grid: (12, 64)  block: 256
// ---------------------------------------------------------------------------
__global__ void oproj_kernel(const float* __restrict__ W,
                             const float* __restrict__ bias,
                             float* __restrict__ out)
{
    const int f0 = blockIdx.x * 64;
    const int m0 = blockIdx.y * 64;
    const int tid = threadIdx.x;
    const int tx = tid & 15, ty = tid >> 4;

    __shared__ float As[64][17];
    __shared__ float Bs[64][17];

    float acc[4][4] = {};
    for (int k0 = 0; k0 < CDIM; k0 += 16) {
        #pragma unroll
        for (int i = 0; i < 4; i++) {
            int idx = tid + i * 256;
            int r = idx >> 4, c = idx & 15;
            As[r][c] = g_ao[(size_t)(m0 + r) * CDIM + k0 + c];
            Bs[r][c] = W[(size_t)(f0 + r) * CDIM + k0 + c];
        }
        __syncthreads();
        #pragma unroll
        for (int k = 0; k < 16; k++) {
            float a[4], b[4];
            #pragma unroll
            for (int i = 0; i < 4; i++) a[i] = As[ty * 4 + i][k];
            #pragma unroll
            for (int j = 0; j < 4; j++) b[j] = Bs[tx * 4 + j][k];
            #pragma unroll
            for (int i = 0; i < 4; i++)
                #pragma unroll
                for (int j = 0; j < 4; j++) acc[i][j] += a[i] * b[j];
        }
        __syncthreads();
    }
    #pragma unroll
    for (int i = 0; i < 4; i++)
        #pragma unroll
        for (int j = 0; j < 4; j++)
            out[(size_t)(m0 + ty * 4 + i) * CDIM + f0 + tx * 4 + j] =
                acc[i][j] + bias[f0 + tx * 4 + j];
}

// ---------------------------------------------------------------------------
extern "C" void kernel_launch(void* const* d_in, const int* in_sizes, int n_in,
                              void* d_out, int out_size)
{
    const float* x   = (const float*)d_in[0];
    const float* ipw = (const float*)d_in[1];
    const float* ipb = (const float*)d_in[2];
    const float* lgs = (const float*)d_in[3];
    const float* lsc = (const float*)d_in[4];
    const float* opw = (const float*)d_in[5];
    const float* opb = (const float*)d_in[6];
    const float* msk = (const float*)d_in[7];
    float* out = (float*)d_out;

    cudaFuncSetAttribute(flash_kernel,
                         cudaFuncAttributeMaxDynamicSharedMemorySize, FLASH_SMEM);

    qkv_kernel<<<dim3(36, 64), 256>>>(x, ipw, ipb, lgs);
    flash_kernel<<<dim3(SEQ / 64, NH, NB), 256, FLASH_SMEM>>>(msk, lsc);
    oproj_kernel<<<dim3(CDIM / 64, 64), 256>>>(opw, opb, out);
}

// round 2
// speedup vs baseline: 1.3581x; 1.3581x over previous
#include <cuda_runtime.h>
#include <math.h>

#define NB 2
#define NH 12
#define HD 64
#define SEQ 2048
#define CDIM 768
#define LSMAX 4.605170185988092f
#define NEPS 1e-12f
#define FPAD 68

// Scratch (allocation-free rule: __device__ globals)
__device__ float g_qn[(size_t)NB*NH*SEQ*HD];   // normalized q * exp(min(ls,MAX)), [N,H,L,D]
__device__ float g_kn[(size_t)NB*NH*SEQ*HD];   // normalized k, [N,H,L,D]
__device__ float g_v [(size_t)NB*NH*SEQ*HD];   // v, [N,H,L,D]
__device__ float g_ao[(size_t)NB*SEQ*CDIM];    // attention output, [N,L,C]

// ---------------------------------------------------------------------------
// Kernel 1: QKV projection, 64x64 tile (one (comp,head) slice), BK=32,
// 128 threads, 8x4 microtile, k-major smem. Fused bias + L2norm + ls fold +
// transpose to [N,H,L,D].
// grid: (36, 64)  block: 128
// ---------------------------------------------------------------------------
__global__ __launch_bounds__(128)
void qkv_kernel(const float* __restrict__ x,
                const float* __restrict__ W,
                const float* __restrict__ bias,
                const float* __restrict__ logit_scale)
{
    const int comp = blockIdx.x / NH;        // 0=q, 1=k, 2=v
    const int h    = blockIdx.x % NH;
    const int m0   = blockIdx.y * 64;
    const int f0   = comp * CDIM + h * HD;
    const int tid  = threadIdx.x;
    const int tx   = tid & 15, ty = tid >> 4;

    __shared__ float As[32][FPAD];   // k-major: As[k][m]
    __shared__ float Bs[32][FPAD];   // k-major: Bs[k][f]

    float acc[8][4] = {};

    for (int k0 = 0; k0 < CDIM; k0 += 32) {
        #pragma unroll
        for (int c = 0; c < 4; c++) {
            int p = tid + c * 128;           // 0..511
            int r = p >> 3;                  // row 0..63
            int kc = (p & 7) * 4;            // k 0,4,..28
            float4 va = *(const float4*)(x + (size_t)(m0 + r) * CDIM + k0 + kc);
            As[kc+0][r] = va.x; As[kc+1][r] = va.y; As[kc+2][r] = va.z; As[kc+3][r] = va.w;
            float4 vb = *(const float4*)(W + (size_t)(f0 + r) * CDIM + k0 + kc);
            Bs[kc+0][r] = vb.x; Bs[kc+1][r] = vb.y; Bs[kc+2][r] = vb.z; Bs[kc+3][r] = vb.w;
        }
        __syncthreads();
        #pragma unroll 8
        for (int k = 0; k < 32; k++) {
            float4 a0 = *(const float4*)&As[k][ty*8];
            float4 a1 = *(const float4*)&As[k][ty*8+4];
            float4 bv = *(const float4*)&Bs[k][tx*4];
            float a[8] = {a0.x,a0.y,a0.z,a0.w,a1.x,a1.y,a1.z,a1.w};
            float b[4] = {bv.x,bv.y,bv.z,bv.w};
            #pragma unroll
            for (int i = 0; i < 8; i++)
                #pragma unroll
                for (int j = 0; j < 4; j++) acc[i][j] += a[i] * b[j];
        }
        __syncthreads();
    }

    // bias
    const float4 bv = *(const float4*)(bias + f0 + tx*4);
    const float bb[4] = {bv.x, bv.y, bv.z, bv.w};
    #pragma unroll
    for (int i = 0; i < 8; i++)
        #pragma unroll
        for (int j = 0; j < 4; j++) acc[i][j] += bb[j];

    // per-row scale: L2 norm (q,k) + logit-scale (q)
    float scl[8];
    #pragma unroll
    for (int i = 0; i < 8; i++) scl[i] = 1.0f;
    if (comp < 2) {
        float lsf = (comp == 0) ? __expf(fminf(logit_scale[h], LSMAX)) : 1.0f;
        #pragma unroll
        for (int i = 0; i < 8; i++) {
            float ss = acc[i][0]*acc[i][0] + acc[i][1]*acc[i][1]
                     + acc[i][2]*acc[i][2] + acc[i][3]*acc[i][3];
            ss += __shfl_xor_sync(0xffffffff, ss, 1);
            ss += __shfl_xor_sync(0xffffffff, ss, 2);
            ss += __shfl_xor_sync(0xffffffff, ss, 4);
            ss += __shfl_xor_sync(0xffffffff, ss, 8);
            scl[i] = lsf / fmaxf(sqrtf(ss), NEPS);
        }
    }

    float* outp = (comp == 0) ? g_qn : (comp == 1) ? g_kn : g_v;
    #pragma unroll
    for (int i = 0; i < 8; i++) {
        int m = m0 + ty*8 + i;
        int n = m >> 11, l = m & (SEQ-1);
        float4 o;
        o.x = acc[i][0]*scl[i]; o.y = acc[i][1]*scl[i];
        o.z = acc[i][2]*scl[i]; o.w = acc[i][3]*scl[i];
        *(float4*)(outp + (((size_t)n*NH + h)*SEQ + l)*HD + tx*4) = o;
    }
}

// ---------------------------------------------------------------------------
// Kernel 2: flash attention, BM=BN=64, D=64, 128 threads, 8x4 microtiles
// grid: (32, 12, 2)  block: 128, dynamic smem 4*64*FPAD floats
// ---------------------------------------------------------------------------
#define FLASH_SMEM (4 * 64 * FPAD * 4)

__global__ __launch_bounds__(128)
void flash_kernel(const float* __restrict__ mask,
                  const float* __restrict__ learned_scale)
{
    extern __shared__ float sm[];
    float (*Qs)[FPAD] = (float(*)[FPAD])sm;            // d-major: Qs[d][m]
    float (*Ks)[FPAD] = Qs + 64;                       // d-major: Ks[d][n]
    float (*Vs)[FPAD] = Ks + 64;                       // row-major: Vs[k][d]
    float (*Ps)[FPAD] = Vs + 64;                       // k-major: Ps[k][m]

    const int qt = blockIdx.x, h = blockIdx.y, n = blockIdx.z;
    const int q0 = qt * 64;
    const int tid = threadIdx.x;
    const int tx = tid & 15, ty = tid >> 4;
    const size_t base = (((size_t)n * NH + h) * SEQ) * HD;

    // load Q transposed (d-major)
    #pragma unroll
    for (int c = 0; c < 8; c++) {
        int p = tid + c * 128;               // 0..1023
        int r = p >> 4;                      // row 0..63
        int kc = (p & 15) * 4;               // d 0,4,..60
        float4 v = *(const float4*)(g_qn + base + (size_t)(q0 + r)*HD + kc);
        Qs[kc+0][r] = v.x; Qs[kc+1][r] = v.y; Qs[kc+2][r] = v.z; Qs[kc+3][r] = v.w;
    }

    float O[8][4] = {};
    float mrow[8], lrow[8];
    #pragma unroll
    for (int i = 0; i < 8; i++) { mrow[i] = -INFINITY; lrow[i] = 0.f; }

    for (int kt = 0; kt < SEQ / 64; kt++) {
        __syncthreads();   // prev PV done (and Q load visible on iter 0)
        #pragma unroll
        for (int c = 0; c < 8; c++) {
            int p = tid + c * 128;
            int r = p >> 4;
            int kc = (p & 15) * 4;
            size_t off = base + (size_t)(kt*64 + r)*HD + kc;
            float4 kv = *(const float4*)(g_kn + off);
            Ks[kc+0][r] = kv.x; Ks[kc+1][r] = kv.y; Ks[kc+2][r] = kv.z; Ks[kc+3][r] = kv.w;
            float4 vv = *(const float4*)(g_v + off);
            *(float4*)&Vs[r][kc] = vv;
        }
        __syncthreads();

        // S = Q K^T  (+ mask)
        float S[8][4] = {};
        #pragma unroll 8
        for (int d = 0; d < 64; d++) {
            float4 a0 = *(const float4*)&Qs[d][ty*8];
            float4 a1 = *(const float4*)&Qs[d][ty*8+4];
            float4 bv = *(const float4*)&Ks[d][tx*4];
            float a[8] = {a0.x,a0.y,a0.z,a0.w,a1.x,a1.y,a1.z,a1.w};
            float b[4] = {bv.x,bv.y,bv.z,bv.w};
            #pragma unroll
            for (int i = 0; i < 8; i++)
                #pragma unroll
                for (int j = 0; j < 4; j++) S[i][j] += a[i] * b[j];
        }
        #pragma unroll
        for (int i = 0; i < 8; i++) {
            float4 mk = *(const float4*)(mask + (size_t)(q0 + ty*8 + i)*SEQ + kt*64 + tx*4);
            S[i][0] += mk.x; S[i][1] += mk.y; S[i][2] += mk.z; S[i][3] += mk.w;
        }

        // online softmax (row group = 16 lanes; xor<=8 stays inside group)
        #pragma unroll
        for (int i = 0; i < 8; i++) {
            float mx = fmaxf(fmaxf(S[i][0], S[i][1]), fmaxf(S[i][2], S[i][3]));
            mx = fmaxf(mx, __shfl_xor_sync(0xffffffff, mx, 1));
            mx = fmaxf(mx, __shfl_xor_sync(0xffffffff, mx, 2));
            mx = fmaxf(mx, __shfl_xor_sync(0xffffffff, mx, 4));
            mx = fmaxf(mx, __shfl_xor_sync(0xffffffff, mx, 8));
            float mnew = fmaxf(mrow[i], mx);
            float alpha = __expf(mrow[i] - mnew);
            mrow[i] = mnew;
            float rs = 0.f;
            #pragma unroll
            for (int j = 0; j < 4; j++) {
                S[i][j] = __expf(S[i][j] - mnew);
                rs += S[i][j];
            }
            rs += __shfl_xor_sync(0xffffffff, rs, 1);
            rs += __shfl_xor_sync(0xffffffff, rs, 2);
            rs += __shfl_xor_sync(0xffffffff, rs, 4);
            rs += __shfl_xor_sync(0xffffffff, rs, 8);
            lrow[i] = lrow[i] * alpha + rs;
            #pragma unroll
            for (int j = 0; j < 4; j++) {
                O[i][j] *= alpha;
                Ps[tx*4+j][ty*8+i] = S[i][j];
            }
        }
        __syncthreads();   // Ps complete before PV

        // O += P V
        #pragma unroll 8
        for (int k = 0; k < 64; k++) {
            float4 a0 = *(const float4*)&Ps[k][ty*8];
            float4 a1 = *(const float4*)&Ps[k][ty*8+4];
            float4 bv = *(const float4*)&Vs[k][tx*4];
            float a[8] = {a0.x,a0.y,a0.z,a0.w,a1.x,a1.y,a1.z,a1.w};
            float b[4] = {bv.x,bv.y,bv.z,bv.w};
            #pragma unroll
            for (int i = 0; i < 8; i++)
                #pragma unroll
                for (int j = 0; j < 4; j++) O[i][j] += a[i] * b[j];
        }
    }

    const float lsc = learned_scale[h];
    #pragma unroll
    for (int i = 0; i < 8; i++) {
        float inv = lsc / lrow[i];
        int l = q0 + ty*8 + i;
        float4 o;
        o.x = O[i][0]*inv; o.y = O[i][1]*inv; o.z = O[i][2]*inv; o.w = O[i][3]*inv;
        *(float4*)(g_ao + ((size_t)n*SEQ + l)*CDIM + h*HD + tx*4) = o;
    }
}

// ---------------------------------------------------------------------------
// Kernel 3: out projection (4096x768 @ 768x768^T + bias) -> d_out
// grid: (12, 64)  block: 128
// ---------------------------------------------------------------------------
__global__ __launch_bounds__(128)
void oproj_kernel(const float* __restrict__ W,
                  const float* __restrict__ bias,
                  float* __restrict__ out)
{
    const int f0 = blockIdx.x * 64;
    const int m0 = blockIdx.y * 64;
    const int tid = threadIdx.x;
    const int tx = tid & 15, ty = tid >> 4;

    __shared__ float As[32][FPAD];
    __shared__ float Bs[32][FPAD];

    float acc[8][4] = {};
    for (int k0 = 0; k0 < CDIM; k0 += 32) {
        #pragma unroll
        for (int c = 0; c < 4; c++) {
            int p = tid + c * 128;
            int r = p >> 3;
            int kc = (p & 7) * 4;
            float4 va = *(const float4*)(g_ao + (size_t)(m0 + r) * CDIM + k0 + kc);
            As[kc+0][r] = va.x; As[kc+1][r] = va.y; As[kc+2][r] = va.z; As[kc+3][r] = va.w;
            float4 vb = *(const float4*)(W + (size_t)(f0 + r) * CDIM + k0 + kc);
            Bs[kc+0][r] = vb.x; Bs[kc+1][r] = vb.y; Bs[kc+2][r] = vb.z; Bs[kc+3][r] = vb.w;
        }
        __syncthreads();
        #pragma unroll 8
        for (int k = 0; k < 32; k++) {
            float4 a0 = *(const float4*)&As[k][ty*8];
            float4 a1 = *(const float4*)&As[k][ty*8+4];
            float4 bv = *(const float4*)&Bs[k][tx*4];
            float a[8] = {a0.x,a0.y,a0.z,a0.w,a1.x,a1.y,a1.z,a1.w};
            float b[4] = {bv.x,bv.y,bv.z,bv.w};
            #pragma unroll
            for (int i = 0; i < 8; i++)
                #pragma unroll
                for (int j = 0; j < 4; j++) acc[i][j] += a[i] * b[j];
        }
        __syncthreads();
    }
    const float4 bv = *(const float4*)(bias + f0 + tx*4);
    const float bb[4] = {bv.x, bv.y, bv.z, bv.w};
    #pragma unroll
    for (int i = 0; i < 8; i++) {
        float4 o;
        o.x = acc[i][0] + bb[0]; o.y = acc[i][1] + bb[1];
        o.z = acc[i][2] + bb[2]; o.w = acc[i][3] + bb[3];
        *(float4*)(out + (size_t)(m0 + ty*8 + i) * CDIM + f0 + tx*4) = o;
    }
}

// ---------------------------------------------------------------------------
extern "C" void kernel_launch(void* const* d_in, const int* in_sizes, int n_in,
                              void* d_out, int out_size)
{
    const float* x   = (const float*)d_in[0];
    const float* ipw = (const float*)d_in[1];
    const float* ipb = (const float*)d_in[2];
    const float* lgs = (const float*)d_in[3];
    const float* lsc = (const float*)d_in[4];
    const float* opw = (const float*)d_in[5];
    const float* opb = (const float*)d_in[6];
    const float* msk = (const float*)d_in[7];
    float* out = (float*)d_out;

    cudaFuncSetAttribute(flash_kernel,
                         cudaFuncAttributeMaxDynamicSharedMemorySize, FLASH_SMEM);

    qkv_kernel<<<dim3(36, 64), 128>>>(x, ipw, ipb, lgs);
    flash_kernel<<<dim3(SEQ / 64, NH, NB), 128, FLASH_SMEM>>>(msk, lsc);
    oproj_kernel<<<dim3(CDIM / 64, 64), 128>>>(opw, opb, out);
}

// round 4
// speedup vs baseline: 3.1368x; 2.3096x over previous
#include <cuda_runtime.h>
#include <cuda_bf16.h>
#include <math.h>
#include <stdint.h>

#define NB 2
#define NH 12
#define HD 64
#define SEQ 2048
#define CDIM 768
#define LSMAX 4.605170185988092f
#define NEPS 1e-12f

// ---------------- scratch (__device__ globals; no allocs allowed) ----------
__device__ __nv_bfloat16 g_qhi[(size_t)NB*NH*SEQ*HD];
__device__ __nv_bfloat16 g_qlo[(size_t)NB*NH*SEQ*HD];
__device__ __nv_bfloat16 g_khi[(size_t)NB*NH*SEQ*HD];
__device__ __nv_bfloat16 g_klo[(size_t)NB*NH*SEQ*HD];
__device__ __nv_bfloat16 g_vb [(size_t)NB*NH*SEQ*HD];
__device__ __nv_bfloat16 g_aohi[(size_t)NB*SEQ*CDIM];
__device__ __nv_bfloat16 g_aolo[(size_t)NB*SEQ*CDIM];

// ---------------- helpers --------------------------------------------------
__device__ __forceinline__ uint32_t smem_u32(const void* p) {
    uint32_t a;
    asm("{ .reg .u64 t; cvta.to.shared.u64 t, %1; cvt.u32.u64 %0, t; }" : "=r"(a) : "l"(p));
    return a;
}
__device__ __forceinline__ void ldsm4(uint32_t r[4], uint32_t a) {
    asm volatile("ldmatrix.sync.aligned.m8n8.x4.shared.b16 {%0,%1,%2,%3}, [%4];"
                 : "=r"(r[0]), "=r"(r[1]), "=r"(r[2]), "=r"(r[3]) : "r"(a));
}
__device__ __forceinline__ void ldsm4t(uint32_t r[4], uint32_t a) {
    asm volatile("ldmatrix.sync.aligned.m8n8.x4.trans.shared.b16 {%0,%1,%2,%3}, [%4];"
                 : "=r"(r[0]), "=r"(r[1]), "=r"(r[2]), "=r"(r[3]) : "r"(a));
}
__device__ __forceinline__ void mma_bf(float d[4], const uint32_t a[4], const uint32_t b[2]) {
    asm volatile("mma.sync.aligned.m16n8k16.row.col.f32.bf16.bf16.f32 "
                 "{%0,%1,%2,%3}, {%4,%5,%6,%7}, {%8,%9}, {%0,%1,%2,%3};"
                 : "+f"(d[0]), "+f"(d[1]), "+f"(d[2]), "+f"(d[3])
                 : "r"(a[0]), "r"(a[1]), "r"(a[2]), "r"(a[3]), "r"(b[0]), "r"(b[1]));
}
__device__ __forceinline__ uint32_t pack2(__nv_bfloat16 a, __nv_bfloat16 b) {
    return (uint32_t)__bfloat16_as_ushort(a) | ((uint32_t)__bfloat16_as_ushort(b) << 16);
}
__device__ __forceinline__ uint32_t packf2(float a, float b) {
    return pack2(__float2bfloat16_rn(a), __float2bfloat16_rn(b));
}
__device__ __forceinline__ void split4(float4 v, uint2& h, uint2& l) {
    __nv_bfloat16 a = __float2bfloat16_rn(v.x), b = __float2bfloat16_rn(v.y),
                  c = __float2bfloat16_rn(v.z), d = __float2bfloat16_rn(v.w);
    h.x = pack2(a, b); h.y = pack2(c, d);
    l.x = packf2(v.x - __bfloat162float(a), v.y - __bfloat162float(b));
    l.y = packf2(v.z - __bfloat162float(c), v.w - __bfloat162float(d));
}

// ---------------- GEMM tile constants -------------------------------------
#define SROW 72                   // bf16 elems per smem row (64 + 8 pad)
#define OFF_AHI 0
#define OFF_ALO 18432
#define OFF_BHI 36864
#define OFF_BLO 55296
#define CPAD 133
#define OFF_BIAS 73728
#define GEMM_SMEM (73728 + 512)

// mainloop: CTA 128x128, K = 768 in 12 chunks of 64. A either fp32 (split on
// stage) or pre-split bf16. B always fp32. Result: d[4][4][4] per thread.
template<bool PRESPLIT>
__device__ __forceinline__ void gemm_mainloop(char* sm, uint32_t smb,
        const float* gA32, const __nv_bfloat16* gAhi, const __nv_bfloat16* gAlo,
        const float* gB32, float d[4][4][4], int tid)
{
    const int wid = tid >> 5, lane = tid & 31;
    const int wm = (wid >> 2) * 64, wn = (wid & 3) * 32;
    const int arow = lane & 15, acol8 = (lane >> 4) << 3;
    const int brow = (lane & 7) | ((lane >> 1) & 8);   // +8 if lane>=16
    const int bcol8 = lane & 8;                        // +8 if bit3

    for (int c = 0; c < CDIM / 64; c++) {
        __syncthreads();
        #pragma unroll
        for (int i = 0; i < 8; i++) {
            int p = tid + i * 256;
            int row = p >> 4, c4 = (p & 15) * 4;
            size_t go = (size_t)row * CDIM + c * 64 + c4;
            uint2 h, l;
            if (PRESPLIT) {
                h = *(const uint2*)(gAhi + go);
                l = *(const uint2*)(gAlo + go);
            } else {
                split4(*(const float4*)(gA32 + go), h, l);
            }
            *(uint2*)(sm + OFF_AHI + (row * SROW + c4) * 2) = h;
            *(uint2*)(sm + OFF_ALO + (row * SROW + c4) * 2) = l;
            split4(*(const float4*)(gB32 + go), h, l);
            *(uint2*)(sm + OFF_BHI + (row * SROW + c4) * 2) = h;
            *(uint2*)(sm + OFF_BLO + (row * SROW + c4) * 2) = l;
        }
        __syncthreads();

        #pragma unroll
        for (int ks = 0; ks < 4; ks++) {
            int k0 = ks * 16;
            uint32_t ah[4][4], al[4][4];
            #pragma unroll
            for (int mt = 0; mt < 4; mt++) {
                uint32_t off = ((wm + mt * 16 + arow) * SROW + k0 + acol8) * 2;
                ldsm4(ah[mt], smb + OFF_AHI + off);
                ldsm4(al[mt], smb + OFF_ALO + off);
            }
            uint32_t bh[2][4], bl[2][4];
            #pragma unroll
            for (int g = 0; g < 2; g++) {
                uint32_t off = ((wn + g * 16 + brow) * SROW + k0 + bcol8) * 2;
                ldsm4(bh[g], smb + OFF_BHI + off);
                ldsm4(bl[g], smb + OFF_BLO + off);
            }
            #pragma unroll
            for (int mt = 0; mt < 4; mt++)
                #pragma unroll
                for (int nt = 0; nt < 4; nt++) {
                    const uint32_t* ph = &bh[nt >> 1][(nt & 1) * 2];
                    const uint32_t* pl = &bl[nt >> 1][(nt & 1) * 2];
                    mma_bf(d[mt][nt], ah[mt], ph);
                    mma_bf(d[mt][nt], ah[mt], pl);
                    mma_bf(d[mt][nt], al[mt], ph);
                }
        }
    }
    __syncthreads();   // all mma reads done before sC overwrites staging smem

    float* sC = (float*)sm;
    const int g = lane >> 2, tg = lane & 3;
    #pragma unroll
    for (int mt = 0; mt < 4; mt++)
        #pragma unroll
        for (int nt = 0; nt < 4; nt++) {
            int r = wm + mt * 16 + g, cc = wn + nt * 8 + tg * 2;
            sC[r * CPAD + cc]           = d[mt][nt][0];
            sC[r * CPAD + cc + 1]       = d[mt][nt][1];
            sC[(r + 8) * CPAD + cc]     = d[mt][nt][2];
            sC[(r + 8) * CPAD + cc + 1] = d[mt][nt][3];
        }
    __syncthreads();
}

// ---------------------------------------------------------------------------
// Kernel 1: QKV projection. grid (18, 32), block 256. Tile 128 rows x 128 f.
// ---------------------------------------------------------------------------
__global__ __launch_bounds__(256, 1)
void qkv_tc(const float* __restrict__ x, const float* __restrict__ W,
            const float* __restrict__ bias, const float* __restrict__ logit_scale)
{
    extern __shared__ __align__(16) char sm[];
    uint32_t smb = smem_u32(sm);
    const int tid = threadIdx.x;
    const int bx = blockIdx.x, by = blockIdx.y;
    const int comp = bx / 6;
    const int h0 = (bx % 6) * 2;
    const int f0 = bx * 128;
    const int m0 = by * 128;

    if (tid < 128) ((float*)(sm + OFF_BIAS))[tid] = bias[f0 + tid];

    float d[4][4][4] = {};
    gemm_mainloop<false>(sm, smb, x + (size_t)m0 * CDIM, nullptr, nullptr,
                         W + (size_t)f0 * CDIM, d, tid);

    // epilogue: bias + L2 norm + scale + split-store to [N,H,L,D]
    const float* sC = (const float*)sm;
    const float* sB = (const float*)(sm + OFF_BIAS);
    const int row = tid & 127, half = tid >> 7;
    const int h = h0 + half;

    float vals[64];
    float ss = 0.f;
    #pragma unroll
    for (int j = 0; j < 64; j++) {
        float v = sC[row * CPAD + half * 64 + j] + sB[half * 64 + j];
        vals[j] = v; ss += v * v;
    }
    float scl = 1.0f;
    if (comp < 2) {
        scl = 1.0f / fmaxf(sqrtf(ss), NEPS);
        if (comp == 0) scl *= __expf(fminf(logit_scale[h], LSMAX));
    }
    const int m = m0 + row;
    const int n = m >> 11, l = m & (SEQ - 1);
    const size_t ob = (((size_t)n * NH + h) * SEQ + l) * HD;

    if (comp == 2) {
        #pragma unroll
        for (int j4 = 0; j4 < 16; j4++) {
            uint2 o;
            o.x = packf2(vals[j4*4+0], vals[j4*4+1]);
            o.y = packf2(vals[j4*4+2], vals[j4*4+3]);
            *(uint2*)(g_vb + ob + j4 * 4) = o;
        }
    } else {
        __nv_bfloat16* ph = (comp == 0) ? g_qhi : g_khi;
        __nv_bfloat16* pl = (comp == 0) ? g_qlo : g_klo;
        #pragma unroll
        for (int j4 = 0; j4 < 16; j4++) {
            float4 v = make_float4(vals[j4*4+0]*scl, vals[j4*4+1]*scl,
                                   vals[j4*4+2]*scl, vals[j4*4+3]*scl);
            uint2 hh, ll;
            split4(v, hh, ll);
            *(uint2*)(ph + ob + j4 * 4) = hh;
            *(uint2*)(pl + ob + j4 * 4) = ll;
        }
    }
}

// ---------------------------------------------------------------------------
// Kernel 3: out projection. grid (6, 32), block 256.
// ---------------------------------------------------------------------------
__global__ __launch_bounds__(256, 1)
void oproj_tc(const float* __restrict__ W, const float* __restrict__ bias,
              float* __restrict__ out)
{
    extern __shared__ __align__(16) char sm[];
    uint32_t smb = smem_u32(sm);
    const int tid = threadIdx.x;
    const int f0 = blockIdx.x * 128;
    const int m0 = blockIdx.y * 128;

    if (tid < 128) ((float*)(sm + OFF_BIAS))[tid] = bias[f0 + tid];

    float d[4][4][4] = {};
    gemm_mainloop<true>(sm, smb, nullptr,
                        g_aohi + (size_t)m0 * CDIM, g_aolo + (size_t)m0 * CDIM,
                        W + (size_t)f0 * CDIM, d, tid);

    const float* sC = (const float*)sm;
    const float* sB = (const float*)(sm + OFF_BIAS);
    const int row = tid & 127, half = tid >> 7;
    float* ob = out + (size_t)(m0 + row) * CDIM + f0 + half * 64;
    #pragma unroll
    for (int j4 = 0; j4 < 16; j4++) {
        float4 o;
        o.x = sC[row * CPAD + half * 64 + j4*4+0] + sB[half * 64 + j4*4+0];
        o.y = sC[row * CPAD + half * 64 + j4*4+1] + sB[half * 64 + j4*4+1];
        o.z = sC[row * CPAD + half * 64 + j4*4+2] + sB[half * 64 + j4*4+2];
        o.w = sC[row * CPAD + half * 64 + j4*4+3] + sB[half * 64 + j4*4+3];
        *(float4*)(ob + j4 * 4) = o;
    }
}

// ---------------------------------------------------------------------------
// Kernel 2: flash attention (HMMA). BM=128, BN=64. grid (16, 12, 2), block 256.
// ---------------------------------------------------------------------------
#define F_QHI 0
#define F_QLO 18432
#define F_KHI 36864
#define F_KLO 46080
#define F_V   55296
#define FLASH_SMEM 64512
#define OPAD 66

__global__ __launch_bounds__(256, 1)
void flash_tc(const float* __restrict__ mask, const float* __restrict__ lscale)
{
    extern __shared__ __align__(16) char sm[];
    uint32_t smb = smem_u32(sm);
    const int tid = threadIdx.x, wid = tid >> 5, lane = tid & 31;
    const int qt = blockIdx.x, h = blockIdx.y, n = blockIdx.z;
    const int q0 = qt * 128;
    const size_t base = (((size_t)n * NH + h) * SEQ) * HD;

    const int arow = lane & 15, acol8 = (lane >> 4) << 3;
    const int brow = (lane & 7) | ((lane >> 1) & 8);
    const int bcol8 = lane & 8;
    const int g_ = lane >> 2, tg = lane & 3;

    // load Q (pre-split bf16) into smem
    #pragma unroll
    for (int i = 0; i < 8; i++) {
        int p = tid + i * 256;
        int row = p >> 4, c4 = (p & 15) * 4;
        size_t go = base + (size_t)(q0 + row) * HD + c4;
        *(uint2*)(sm + F_QHI + (row * SROW + c4) * 2) = *(const uint2*)(g_qhi + go);
        *(uint2*)(sm + F_QLO + (row * SROW + c4) * 2) = *(const uint2*)(g_qlo + go);
    }

    float O[8][4] = {};
    float m0r = -INFINITY, m1r = -INFINITY, l0r = 0.f, l1r = 0.f;

    for (int kt = 0; kt < SEQ / 64; kt++) {
        __syncthreads();
        #pragma unroll
        for (int i = 0; i < 4; i++) {
            int p = tid + i * 256;
            int row = p >> 4, c4 = (p & 15) * 4;
            size_t go = base + (size_t)(kt * 64 + row) * HD + c4;
            *(uint2*)(sm + F_KHI + (row * SROW + c4) * 2) = *(const uint2*)(g_khi + go);
            *(uint2*)(sm + F_KLO + (row * SROW + c4) * 2) = *(const uint2*)(g_klo + go);
            *(uint2*)(sm + F_V   + (row * SROW + c4) * 2) = *(const uint2*)(g_vb  + go);
        }
        __syncthreads();

        // S = Q K^T (3xBF16)
        float S[8][4] = {};
        #pragma unroll
        for (int ks = 0; ks < 4; ks++) {
            int k0 = ks * 16;
            uint32_t qh[4], ql[4];
            uint32_t qoff = ((wid * 16 + arow) * SROW + k0 + acol8) * 2;
            ldsm4(qh, smb + F_QHI + qoff);
            ldsm4(ql, smb + F_QLO + qoff);
            uint32_t kh[4][4], kl[4][4];
            #pragma unroll
            for (int g = 0; g < 4; g++) {
                uint32_t off = ((g * 16 + brow) * SROW + k0 + bcol8) * 2;
                ldsm4(kh[g], smb + F_KHI + off);
                ldsm4(kl[g], smb + F_KLO + off);
            }
            #pragma unroll
            for (int nt = 0; nt < 8; nt++) {
                const uint32_t* ph = &kh[nt >> 1][(nt & 1) * 2];
                const uint32_t* pl = &kl[nt >> 1][(nt & 1) * 2];
                mma_bf(S[nt], qh, ph);
                mma_bf(S[nt], qh, pl);
                mma_bf(S[nt], ql, ph);
            }
        }

        // additive mask
        const int r0 = q0 + wid * 16 + g_, r1 = r0 + 8;
        #pragma unroll
        for (int nt = 0; nt < 8; nt++) {
            int cc = kt * 64 + nt * 8 + tg * 2;
            float2 a = *(const float2*)(mask + (size_t)r0 * SEQ + cc);
            float2 b = *(const float2*)(mask + (size_t)r1 * SEQ + cc);
            S[nt][0] += a.x; S[nt][1] += a.y; S[nt][2] += b.x; S[nt][3] += b.y;
        }

        // online softmax (rows g_, g_+8; 4 threads/row -> xor 1,2)
        float mx0 = -INFINITY, mx1 = -INFINITY;
        #pragma unroll
        for (int nt = 0; nt < 8; nt++) {
            mx0 = fmaxf(mx0, fmaxf(S[nt][0], S[nt][1]));
            mx1 = fmaxf(mx1, fmaxf(S[nt][2], S[nt][3]));
        }
        mx0 = fmaxf(mx0, __shfl_xor_sync(0xffffffff, mx0, 1));
        mx0 = fmaxf(mx0, __shfl_xor_sync(0xffffffff, mx0, 2));
        mx1 = fmaxf(mx1, __shfl_xor_sync(0xffffffff, mx1, 1));
        mx1 = fmaxf(mx1, __shfl_xor_sync(0xffffffff, mx1, 2));
        float mn0 = fmaxf(m0r, mx0), mn1 = fmaxf(m1r, mx1);
        float al0 = __expf(m0r - mn0), al1 = __expf(m1r - mn1);
        m0r = mn0; m1r = mn1;
        float s0 = 0.f, s1 = 0.f;
        #pragma unroll
        for (int nt = 0; nt < 8; nt++) {
            S[nt][0] = __expf(S[nt][0] - mn0); s0 += S[nt][0];
            S[nt][1] = __expf(S[nt][1] - mn0); s0 += S[nt][1];
            S[nt][2] = __expf(S[nt][2] - mn1); s1 += S[nt][2];
            S[nt][3] = __expf(S[nt][3] - mn1); s1 += S[nt][3];
        }
        s0 += __shfl_xor_sync(0xffffffff, s0, 1);
        s0 += __shfl_xor_sync(0xffffffff, s0, 2);
        s1 += __shfl_xor_sync(0xffffffff, s1, 1);
        s1 += __shfl_xor_sync(0xffffffff, s1, 2);
        l0r = l0r * al0 + s0;
        l1r = l1r * al1 + s1;
        #pragma unroll
        for (int dt = 0; dt < 8; dt++) {
            O[dt][0] *= al0; O[dt][1] *= al0; O[dt][2] *= al1; O[dt][3] *= al1;
        }

        // P -> bf16 A-frags (FA2 register reuse)
        uint32_t pa[4][4];
        #pragma unroll
        for (int k2 = 0; k2 < 4; k2++) {
            pa[k2][0] = packf2(S[2*k2][0],   S[2*k2][1]);
            pa[k2][1] = packf2(S[2*k2][2],   S[2*k2][3]);
            pa[k2][2] = packf2(S[2*k2+1][0], S[2*k2+1][1]);
            pa[k2][3] = packf2(S[2*k2+1][2], S[2*k2+1][3]);
        }
        // O += P V  (V via ldmatrix.trans)
        #pragma unroll
        for (int ks = 0; ks < 4; ks++) {
            uint32_t vb[4][4];
            #pragma unroll
            for (int g = 0; g < 4; g++) {
                uint32_t off = ((ks * 16 + arow) * SROW + g * 16 + acol8) * 2;
                ldsm4t(vb[g], smb + F_V + off);
            }
            #pragma unroll
            for (int dt = 0; dt < 8; dt++)
                mma_bf(O[dt], pa[ks], &vb[dt >> 1][(dt & 1) * 2]);
        }
    }

    // epilogue: 1/l * learned_scale, stage via smem, split-store to g_ao*
    const float lsc = lscale[h];
    const float inv0 = lsc / l0r, inv1 = lsc / l1r;
    __syncthreads();
    float* sO = (float*)sm;
    #pragma unroll
    for (int dt = 0; dt < 8; dt++) {
        int r = wid * 16 + g_, cc = dt * 8 + tg * 2;
        sO[r * OPAD + cc]           = O[dt][0] * inv0;
        sO[r * OPAD + cc + 1]       = O[dt][1] * inv0;
        sO[(r + 8) * OPAD + cc]     = O[dt][2] * inv1;
        sO[(r + 8) * OPAD + cc + 1] = O[dt][3] * inv1;
    }
    __syncthreads();
    const int row = tid & 127, half = tid >> 7;
    const size_t ob = ((size_t)n * SEQ + q0 + row) * CDIM + h * HD + half * 32;
    #pragma unroll
    for (int j4 = 0; j4 < 8; j4++) {
        float4 v;
        v.x = sO[row * OPAD + half * 32 + j4*4+0];
        v.y = sO[row * OPAD + half * 32 + j4*4+1];
        v.z = sO[row * OPAD + half * 32 + j4*4+2];
        v.w = sO[row * OPAD + half * 32 + j4*4+3];
        uint2 hh, ll;
        split4(v, hh, ll);
        *(uint2*)(g_aohi + ob + j4 * 4) = hh;
        *(uint2*)(g_aolo + ob + j4 * 4) = ll;
    }
}

// ---------------------------------------------------------------------------
extern "C" void kernel_launch(void* const* d_in, const int* in_sizes, int n_in,
                              void* d_out, int out_size)
{
    const float* x   = (const float*)d_in[0];
    const float* ipw = (const float*)d_in[1];
    const float* ipb = (const float*)d_in[2];
    const float* lgs = (const float*)d_in[3];
    const float* lsc = (const float*)d_in[4];
    const float* opw = (const float*)d_in[5];
    const float* opb = (const float*)d_in[6];
    const float* msk = (const float*)d_in[7];
    float* out = (float*)d_out;

    cudaFuncSetAttribute(qkv_tc,   cudaFuncAttributeMaxDynamicSharedMemorySize, GEMM_SMEM);
    cudaFuncSetAttribute(oproj_tc, cudaFuncAttributeMaxDynamicSharedMemorySize, GEMM_SMEM);
    cudaFuncSetAttribute(flash_tc, cudaFuncAttributeMaxDynamicSharedMemorySize, FLASH_SMEM);

    qkv_tc<<<dim3(18, 32), 256, GEMM_SMEM>>>(x, ipw, ipb, lgs);
    flash_tc<<<dim3(SEQ / 128, NH, NB), 256, FLASH_SMEM>>>(msk, lsc);
    oproj_tc<<<dim3(6, 32), 256, GEMM_SMEM>>>(opw, opb, out);
}

// round 7
// speedup vs baseline: 3.3216x; 1.0589x over previous
#include <cuda_runtime.h>
#include <cuda_bf16.h>
#include <math.h>
#include <stdint.h>

#define NB 2
#define NH 12
#define HD 64
#define SEQ 2048
#define CDIM 768
#define LSMAX 4.605170185988092f
#define NEPS 1e-12f

// ---------------- scratch (__device__ globals; no allocs allowed) ----------
__device__ __nv_bfloat16 g_qhi[(size_t)NB*NH*SEQ*HD];
__device__ __nv_bfloat16 g_qlo[(size_t)NB*NH*SEQ*HD];
__device__ __nv_bfloat16 g_khi[(size_t)NB*NH*SEQ*HD];
__device__ __nv_bfloat16 g_klo[(size_t)NB*NH*SEQ*HD];
__device__ __nv_bfloat16 g_vb [(size_t)NB*NH*SEQ*HD];
__device__ __nv_bfloat16 g_aohi[(size_t)NB*SEQ*CDIM];
__device__ __nv_bfloat16 g_aolo[(size_t)NB*SEQ*CDIM];

// ---------------- helpers --------------------------------------------------
__device__ __forceinline__ uint32_t smem_u32(const void* p) {
    uint32_t a;
    asm("{ .reg .u64 t; cvta.to.shared.u64 t, %1; cvt.u32.u64 %0, t; }" : "=r"(a) : "l"(p));
    return a;
}
__device__ __forceinline__ void ldsm4(uint32_t r[4], uint32_t a) {
    asm volatile("ldmatrix.sync.aligned.m8n8.x4.shared.b16 {%0,%1,%2,%3}, [%4];"
                 : "=r"(r[0]), "=r"(r[1]), "=r"(r[2]), "=r"(r[3]) : "r"(a));
}
__device__ __forceinline__ void ldsm4t(uint32_t r[4], uint32_t a) {
    asm volatile("ldmatrix.sync.aligned.m8n8.x4.trans.shared.b16 {%0,%1,%2,%3}, [%4];"
                 : "=r"(r[0]), "=r"(r[1]), "=r"(r[2]), "=r"(r[3]) : "r"(a));
}
__device__ __forceinline__ void mma_bf(float d[4], const uint32_t a[4], const uint32_t b[2]) {
    asm volatile("mma.sync.aligned.m16n8k16.row.col.f32.bf16.bf16.f32 "
                 "{%0,%1,%2,%3}, {%4,%5,%6,%7}, {%8,%9}, {%0,%1,%2,%3};"
                 : "+f"(d[0]), "+f"(d[1]), "+f"(d[2]), "+f"(d[3])
                 : "r"(a[0]), "r"(a[1]), "r"(a[2]), "r"(a[3]), "r"(b[0]), "r"(b[1]));
}
__device__ __forceinline__ uint32_t pack2(__nv_bfloat16 a, __nv_bfloat16 b) {
    return (uint32_t)__bfloat16_as_ushort(a) | ((uint32_t)__bfloat16_as_ushort(b) << 16);
}
__device__ __forceinline__ uint32_t packf2(float a, float b) {
    return pack2(__float2bfloat16_rn(a), __float2bfloat16_rn(b));
}
__device__ __forceinline__ void split4(float4 v, uint2& h, uint2& l) {
    __nv_bfloat16 a = __float2bfloat16_rn(v.x), b = __float2bfloat16_rn(v.y),
                  c = __float2bfloat16_rn(v.z), d = __float2bfloat16_rn(v.w);
    h.x = pack2(a, b); h.y = pack2(c, d);
    l.x = packf2(v.x - __bfloat162float(a), v.y - __bfloat162float(b));
    l.y = packf2(v.z - __bfloat162float(c), v.w - __bfloat162float(d));
}
__device__ __forceinline__ void cpa16(uint32_t dst, const void* src) {
    asm volatile("cp.async.cg.shared.global [%0], [%1], 16;" :: "r"(dst), "l"(src));
}
#define CP_COMMIT() asm volatile("cp.async.commit_group;" ::: "memory")
#define CP_WAIT1()  asm volatile("cp.async.wait_group 1;" ::: "memory")
#define CP_WAIT0()  asm volatile("cp.async.wait_group 0;" ::: "memory")

// ---------------- GEMM tile constants (R4 layout) --------------------------
#define SROW 72                   // bf16 elems per smem row (64 + 8 pad)
#define OFF_AHI 0
#define OFF_ALO 18432
#define OFF_BHI 36864
#define OFF_BLO 55296
#define CPAD 133
#define OFF_BIAS 73728
#define GEMM_SMEM (73728 + 512)

// mainloop: CTA 128x128, K = 768 in 12 chunks of 64. A either fp32 (split on
// stage) or pre-split bf16. B always fp32. Result: d[4][4][4] per thread.
template<bool PRESPLIT>
__device__ __forceinline__ void gemm_mainloop(char* sm, uint32_t smb,
        const float* gA32, const __nv_bfloat16* gAhi, const __nv_bfloat16* gAlo,
        const float* gB32, float d[4][4][4], int tid)
{
    const int wid = tid >> 5, lane = tid & 31;
    const int wm = (wid >> 2) * 64, wn = (wid & 3) * 32;
    const int arow = lane & 15, acol8 = (lane >> 4) << 3;
    const int brow = (lane & 7) | ((lane >> 1) & 8);   // +8 if lane>=16
    const int bcol8 = lane & 8;                        // +8 if bit3

    for (int c = 0; c < CDIM / 64; c++) {
        __syncthreads();
        #pragma unroll
        for (int i = 0; i < 8; i++) {
            int p = tid + i * 256;
            int row = p >> 4, c4 = (p & 15) * 4;
            size_t go = (size_t)row * CDIM + c * 64 + c4;
            uint2 h, l;
            if (PRESPLIT) {
                h = *(const uint2*)(gAhi + go);
                l = *(const uint2*)(gAlo + go);
            } else {
                split4(*(const float4*)(gA32 + go), h, l);
            }
            *(uint2*)(sm + OFF_AHI + (row * SROW + c4) * 2) = h;
            *(uint2*)(sm + OFF_ALO + (row * SROW + c4) * 2) = l;
            split4(*(const float4*)(gB32 + go), h, l);
            *(uint2*)(sm + OFF_BHI + (row * SROW + c4) * 2) = h;
            *(uint2*)(sm + OFF_BLO + (row * SROW + c4) * 2) = l;
        }
        __syncthreads();

        #pragma unroll
        for (int ks = 0; ks < 4; ks++) {
            int k0 = ks * 16;
            uint32_t ah[4][4], al[4][4];
            #pragma unroll
            for (int mt = 0; mt < 4; mt++) {
                uint32_t off = ((wm + mt * 16 + arow) * SROW + k0 + acol8) * 2;
                ldsm4(ah[mt], smb + OFF_AHI + off);
                ldsm4(al[mt], smb + OFF_ALO + off);
            }
            uint32_t bh[2][4], bl[2][4];
            #pragma unroll
            for (int g = 0; g < 2; g++) {
                uint32_t off = ((wn + g * 16 + brow) * SROW + k0 + bcol8) * 2;
                ldsm4(bh[g], smb + OFF_BHI + off);
                ldsm4(bl[g], smb + OFF_BLO + off);
            }
            #pragma unroll
            for (int mt = 0; mt < 4; mt++)
                #pragma unroll
                for (int nt = 0; nt < 4; nt++) {
                    const uint32_t* ph = &bh[nt >> 1][(nt & 1) * 2];
                    const uint32_t* pl = &bl[nt >> 1][(nt & 1) * 2];
                    mma_bf(d[mt][nt], ah[mt], ph);
                    mma_bf(d[mt][nt], ah[mt], pl);
                    mma_bf(d[mt][nt], al[mt], ph);
                }
        }
    }
    __syncthreads();   // all mma reads done before sC overwrites staging smem

    float* sC = (float*)sm;
    const int g = lane >> 2, tg = lane & 3;
    #pragma unroll
    for (int mt = 0; mt < 4; mt++)
        #pragma unroll
        for (int nt = 0; nt < 4; nt++) {
            int r = wm + mt * 16 + g, cc = wn + nt * 8 + tg * 2;
            sC[r * CPAD + cc]           = d[mt][nt][0];
            sC[r * CPAD + cc + 1]       = d[mt][nt][1];
            sC[(r + 8) * CPAD + cc]     = d[mt][nt][2];
            sC[(r + 8) * CPAD + cc + 1] = d[mt][nt][3];
        }
    __syncthreads();
}

// ---------------------------------------------------------------------------
// Kernel 1: QKV projection. grid (18, 32), block 256. Tile 128 rows x 128 f.
// ---------------------------------------------------------------------------
__global__ __launch_bounds__(256, 1)
void qkv_tc(const float* __restrict__ x, const float* __restrict__ W,
            const float* __restrict__ bias, const float* __restrict__ logit_scale)
{
    extern __shared__ __align__(16) char sm[];
    uint32_t smb = smem_u32(sm);
    const int tid = threadIdx.x;
    const int bx = blockIdx.x, by = blockIdx.y;
    const int comp = bx / 6;
    const int h0 = (bx % 6) * 2;
    const int f0 = bx * 128;
    const int m0 = by * 128;

    if (tid < 128) ((float*)(sm + OFF_BIAS))[tid] = bias[f0 + tid];

    float d[4][4][4] = {};
    gemm_mainloop<false>(sm, smb, x + (size_t)m0 * CDIM, nullptr, nullptr,
                         W + (size_t)f0 * CDIM, d, tid);

    // epilogue: bias + L2 norm + scale + split-store to [N,H,L,D]
    const float* sC = (const float*)sm;
    const float* sB = (const float*)(sm + OFF_BIAS);
    const int row = tid & 127, half = tid >> 7;
    const int h = h0 + half;

    float vals[64];
    float ss = 0.f;
    #pragma unroll
    for (int j = 0; j < 64; j++) {
        float v = sC[row * CPAD + half * 64 + j] + sB[half * 64 + j];
        vals[j] = v; ss += v * v;
    }
    float scl = 1.0f;
    if (comp < 2) {
        scl = 1.0f / fmaxf(sqrtf(ss), NEPS);
        if (comp == 0) scl *= __expf(fminf(logit_scale[h], LSMAX));
    }
    const int m = m0 + row;
    const int n = m >> 11, l = m & (SEQ - 1);
    const size_t ob = (((size_t)n * NH + h) * SEQ + l) * HD;

    if (comp == 2) {
        #pragma unroll
        for (int j4 = 0; j4 < 16; j4++) {
            uint2 o;
            o.x = packf2(vals[j4*4+0], vals[j4*4+1]);
            o.y = packf2(vals[j4*4+2], vals[j4*4+3]);
            *(uint2*)(g_vb + ob + j4 * 4) = o;
        }
    } else {
        __nv_bfloat16* ph = (comp == 0) ? g_qhi : g_khi;
        __nv_bfloat16* pl = (comp == 0) ? g_qlo : g_klo;
        #pragma unroll
        for (int j4 = 0; j4 < 16; j4++) {
            float4 v = make_float4(vals[j4*4+0]*scl, vals[j4*4+1]*scl,
                                   vals[j4*4+2]*scl, vals[j4*4+3]*scl);
            uint2 hh, ll;
            split4(v, hh, ll);
            *(uint2*)(ph + ob + j4 * 4) = hh;
            *(uint2*)(pl + ob + j4 * 4) = ll;
        }
    }
}

// ---------------------------------------------------------------------------
// Kernel 3: out projection. grid (6, 32), block 256.
// ---------------------------------------------------------------------------
__global__ __launch_bounds__(256, 1)
void oproj_tc(const float* __restrict__ W, const float* __restrict__ bias,
              float* __restrict__ out)
{
    extern __shared__ __align__(16) char sm[];
    uint32_t smb = smem_u32(sm);
    const int tid = threadIdx.x;
    const int f0 = blockIdx.x * 128;
    const int m0 = blockIdx.y * 128;

    if (tid < 128) ((float*)(sm + OFF_BIAS))[tid] = bias[f0 + tid];

    float d[4][4][4] = {};
    gemm_mainloop<true>(sm, smb, nullptr,
                        g_aohi + (size_t)m0 * CDIM, g_aolo + (size_t)m0 * CDIM,
                        W + (size_t)f0 * CDIM, d, tid);

    const float* sC = (const float*)sm;
    const float* sB = (const float*)(sm + OFF_BIAS);
    const int row = tid & 127, half = tid >> 7;
    float* ob = out + (size_t)(m0 + row) * CDIM + f0 + half * 64;
    #pragma unroll
    for (int j4 = 0; j4 < 16; j4++) {
        float4 o;
        o.x = sC[row * CPAD + half * 64 + j4*4+0] + sB[half * 64 + j4*4+0];
        o.y = sC[row * CPAD + half * 64 + j4*4+1] + sB[half * 64 + j4*4+1];
        o.z = sC[row * CPAD + half * 64 + j4*4+2] + sB[half * 64 + j4*4+2];
        o.w = sC[row * CPAD + half * 64 + j4*4+3] + sB[half * 64 + j4*4+3];
        *(float4*)(ob + j4 * 4) = o;
    }
}

// ---------------------------------------------------------------------------
// Kernel 2: flash attention (HMMA, R4 math) + cp.async double-buffered K/V.
// BM=128, BN=64. grid (16, 12, 2), block 256.
// ---------------------------------------------------------------------------
#define F_QHI 0
#define F_QLO 18432
#define FKV(s) (36864 + (s)*27648)
#define FK_HI 0
#define FK_LO 9216
#define FV    18432
#define FLASH_SMEM 92160
#define OPAD 66

__device__ __forceinline__ void f_load_stage(uint32_t smb, int s, size_t base,
                                             int kt, int tid)
{
    #pragma unroll
    for (int i = 0; i < 2; i++) {
        int p = tid + i * 256;               // 0..511
        int row = p >> 3, ch = p & 7;
        size_t go = base + (size_t)(kt * 64 + row) * HD + ch * 8;
        uint32_t so = (uint32_t)(row * SROW + ch * 8) * 2;
        cpa16(smb + FKV(s) + FK_HI + so, g_khi + go);
        cpa16(smb + FKV(s) + FK_LO + so, g_klo + go);
        cpa16(smb + FKV(s) + FV    + so, g_vb  + go);
    }
}

__global__ __launch_bounds__(256, 1)
void flash_tc(const float* __restrict__ mask, const float* __restrict__ lscale)
{
    extern __shared__ __align__(16) char sm[];
    uint32_t smb = smem_u32(sm);
    const int tid = threadIdx.x, wid = tid >> 5, lane = tid & 31;
    const int qt = blockIdx.x, h = blockIdx.y, n = blockIdx.z;
    const int q0 = qt * 128;
    const size_t base = (((size_t)n * NH + h) * SEQ) * HD;

    const int arow = lane & 15, acol8 = (lane >> 4) << 3;
    const int brow = (lane & 7) | ((lane >> 1) & 8);
    const int bcol8 = lane & 8;
    const int g_ = lane >> 2, tg = lane & 3;

    // load Q (pre-split bf16) into smem
    #pragma unroll
    for (int i = 0; i < 8; i++) {
        int p = tid + i * 256;
        int row = p >> 4, c4 = (p & 15) * 4;
        size_t go = base + (size_t)(q0 + row) * HD + c4;
        uint32_t so = (uint32_t)(row * SROW + c4) * 2;
        *(uint2*)(sm + F_QHI + so) = *(const uint2*)(g_qhi + go);
        *(uint2*)(sm + F_QLO + so) = *(const uint2*)(g_qlo + go);
    }

    f_load_stage(smb, 0, base, 0, tid);
    CP_COMMIT();

    float O[8][4] = {};
    float m0r = -INFINITY, m1r = -INFINITY, l0r = 0.f, l1r = 0.f;

    for (int kt = 0; kt < SEQ / 64; kt++) {
        const int s = kt & 1;
        if (kt < SEQ / 64 - 1) {
            f_load_stage(smb, s ^ 1, base, kt + 1, tid);
            CP_COMMIT();
            CP_WAIT1();
        } else {
            CP_WAIT0();
        }
        __syncthreads();

        // S = Q K^T (3xBF16)
        float S[8][4] = {};
        #pragma unroll
        for (int ks = 0; ks < 4; ks++) {
            int k0 = ks * 16;
            uint32_t qh[4], ql[4];
            uint32_t qoff = ((wid * 16 + arow) * SROW + k0 + acol8) * 2;
            ldsm4(qh, smb + F_QHI + qoff);
            ldsm4(ql, smb + F_QLO + qoff);
            uint32_t kh[4][4], kl[4][4];
            #pragma unroll
            for (int g = 0; g < 4; g++) {
                uint32_t off = ((g * 16 + brow) * SROW + k0 + bcol8) * 2;
                ldsm4(kh[g], smb + FKV(s) + FK_HI + off);
                ldsm4(kl[g], smb + FKV(s) + FK_LO + off);
            }
            #pragma unroll
            for (int nt = 0; nt < 8; nt++) {
                const uint32_t* ph = &kh[nt >> 1][(nt & 1) * 2];
                const uint32_t* pl = &kl[nt >> 1][(nt & 1) * 2];
                mma_bf(S[nt], qh, ph);
                mma_bf(S[nt], qh, pl);
                mma_bf(S[nt], ql, ph);
            }
        }

        // additive mask
        const int r0 = q0 + wid * 16 + g_, r1 = r0 + 8;
        #pragma unroll
        for (int nt = 0; nt < 8; nt++) {
            int cc = kt * 64 + nt * 8 + tg * 2;
            float2 a = *(const float2*)(mask + (size_t)r0 * SEQ + cc);
            float2 b = *(const float2*)(mask + (size_t)r1 * SEQ + cc);
            S[nt][0] += a.x; S[nt][1] += a.y; S[nt][2] += b.x; S[nt][3] += b.y;
        }

        // online softmax (rows g_, g_+8; 4 threads/row -> xor 1,2)
        float mx0 = -INFINITY, mx1 = -INFINITY;
        #pragma unroll
        for (int nt = 0; nt < 8; nt++) {
            mx0 = fmaxf(mx0, fmaxf(S[nt][0], S[nt][1]));
            mx1 = fmaxf(mx1, fmaxf(S[nt][2], S[nt][3]));
        }
        mx0 = fmaxf(mx0, __shfl_xor_sync(0xffffffff, mx0, 1));
        mx0 = fmaxf(mx0, __shfl_xor_sync(0xffffffff, mx0, 2));
        mx1 = fmaxf(mx1, __shfl_xor_sync(0xffffffff, mx1, 1));
        mx1 = fmaxf(mx1, __shfl_xor_sync(0xffffffff, mx1, 2));
        float mn0 = fmaxf(m0r, mx0), mn1 = fmaxf(m1r, mx1);
        float al0 = __expf(m0r - mn0), al1 = __expf(m1r - mn1);
        m0r = mn0; m1r = mn1;
        float s0 = 0.f, s1 = 0.f;
        #pragma unroll
        for (int nt = 0; nt < 8; nt++) {
            S[nt][0] = __expf(S[nt][0] - mn0); s0 += S[nt][0];
            S[nt][1] = __expf(S[nt][1] - mn0); s0 += S[nt][1];
            S[nt][2] = __expf(S[nt][2] - mn1); s1 += S[nt][2];
            S[nt][3] = __expf(S[nt][3] - mn1); s1 += S[nt][3];
        }
        s0 += __shfl_xor_sync(0xffffffff, s0, 1);
        s0 += __shfl_xor_sync(0xffffffff, s0, 2);
        s1 += __shfl_xor_sync(0xffffffff, s1, 1);
        s1 += __shfl_xor_sync(0xffffffff, s1, 2);
        l0r = l0r * al0 + s0;
        l1r = l1r * al1 + s1;
        #pragma unroll
        for (int dt = 0; dt < 8; dt++) {
            O[dt][0] *= al0; O[dt][1] *= al0; O[dt][2] *= al1; O[dt][3] *= al1;
        }

        // P -> bf16 A-frags (FA2 register reuse)
        uint32_t pa[4][4];
        #pragma unroll
        for (int k2 = 0; k2 < 4; k2++) {
            pa[k2][0] = packf2(S[2*k2][0],   S[2*k2][1]);
            pa[k2][1] = packf2(S[2*k2][2],   S[2*k2][3]);
            pa[k2][2] = packf2(S[2*k2+1][0], S[2*k2+1][1]);
            pa[k2][3] = packf2(S[2*k2+1][2], S[2*k2+1][3]);
        }
        // O += P V  (V via ldmatrix.trans)
        #pragma unroll
        for (int ks = 0; ks < 4; ks++) {
            uint32_t vb[4][4];
            #pragma unroll
            for (int g = 0; g < 4; g++) {
                uint32_t off = ((ks * 16 + arow) * SROW + g * 16 + acol8) * 2;
                ldsm4t(vb[g], smb + FKV(s) + FV + off);
            }
            #pragma unroll
            for (int dt = 0; dt < 8; dt++)
                mma_bf(O[dt], pa[ks], &vb[dt >> 1][(dt & 1) * 2]);
        }
        __syncthreads();   // all reads of stage s done before next overwrite
    }

    // epilogue: 1/l * learned_scale, stage via smem, split-store to g_ao*
    const float lsc = lscale[h];
    const float inv0 = lsc / l0r, inv1 = lsc / l1r;
    float* sO = (float*)sm;
    #pragma unroll
    for (int dt = 0; dt < 8; dt++) {
        int r = wid * 16 + g_, cc = dt * 8 + tg * 2;
        sO[r * OPAD + cc]           = O[dt][0] * inv0;
        sO[r * OPAD + cc + 1]       = O[dt][1] * inv0;
        sO[(r + 8) * OPAD + cc]     = O[dt][2] * inv1;
        sO[(r + 8) * OPAD + cc + 1] = O[dt][3] * inv1;
    }
    __syncthreads();
    const int row = tid & 127, half = tid >> 7;
    const size_t ob = ((size_t)n * SEQ + q0 + row) * CDIM + h * HD + half * 32;
    #pragma unroll
    for (int j4 = 0; j4 < 8; j4++) {
        float4 v;
        v.x = sO[row * OPAD + half * 32 + j4*4+0];
        v.y = sO[row * OPAD + half * 32 + j4*4+1];
        v.z = sO[row * OPAD + half * 32 + j4*4+2];
        v.w = sO[row * OPAD + half * 32 + j4*4+3];
        uint2 hh, ll;
        split4(v, hh, ll);
        *(uint2*)(g_aohi + ob + j4 * 4) = hh;
        *(uint2*)(g_aolo + ob + j4 * 4) = ll;
    }
}

// ---------------------------------------------------------------------------
extern "C" void kernel_launch(void* const* d_in, const int* in_sizes, int n_in,
                              void* d_out, int out_size)
{
    const float* x   = (const float*)d_in[0];
    const float* ipw = (const float*)d_in[1];
    const float* ipb = (const float*)d_in[2];
    const float* lgs = (const float*)d_in[3];
    const float* lsc = (const float*)d_in[4];
    const float* opw = (const float*)d_in[5];
    const float* opb = (const float*)d_in[6];
    const float* msk = (const float*)d_in[7];
    float* out = (float*)d_out;

    cudaFuncSetAttribute(qkv_tc,   cudaFuncAttributeMaxDynamicSharedMemorySize, GEMM_SMEM);
    cudaFuncSetAttribute(oproj_tc, cudaFuncAttributeMaxDynamicSharedMemorySize, GEMM_SMEM);
    cudaFuncSetAttribute(flash_tc, cudaFuncAttributeMaxDynamicSharedMemorySize, FLASH_SMEM);

    qkv_tc<<<dim3(18, 32), 256, GEMM_SMEM>>>(x, ipw, ipb, lgs);
    flash_tc<<<dim3(SEQ / 128, NH, NB), 256, FLASH_SMEM>>>(msk, lsc);
    oproj_tc<<<dim3(6, 32), 256, GEMM_SMEM>>>(opw, opb, out);
}